// round 5
// baseline (speedup 1.0000x reference)
#include <cuda_runtime.h>

#define VOCAB 32000
#define BATCH 4
#define SEQ   2048
#define NVEC  (VOCAB / 4)           // 8000 float4 per row
#define TOTAL (BATCH * SEQ)         // 8192 rows
#define N4    ((BATCH * VOCAB) / 4) // 32000 int4

// Scratch state. Zero-initialized at module load; the kernel restores all of
// it to zero before exiting, so every launch (correctness run and every graph
// replay) sees identical initial state.
__device__ int      g_hist[BATCH * VOCAB];
__device__ unsigned g_next = 0;   // dynamic row-stealing cursor
__device__ unsigned g_done = 0;   // CTAs that finished all argmax work
__device__ unsigned g_fin  = 0;   // CTAs that finished finalize

__global__ __launch_bounds__(256, 8)
void fused_persistent_kernel(const float* __restrict__ logits,
                             float* __restrict__ out) {
    const int tid = threadIdx.x;
    const int wid = tid >> 5;
    const int lid = tid & 31;

    __shared__ float    s_val[8];
    __shared__ int      s_idx[8];
    __shared__ unsigned s_row;

    // ---------- phase 1: dynamic row stealing, argmax + hist ----------
    for (;;) {
        if (tid == 0) s_row = atomicAdd(&g_next, 1u);
        __syncthreads();
        const unsigned row = s_row;
        if (row >= TOTAL) break;

        const float4* __restrict__ p =
            reinterpret_cast<const float4*>(logits + (size_t)row * VOCAB);

        float best = -3.402823466e+38f;
        int   bidx = 0;

        // Streaming float4 scan; strict '>' keeps first (lowest-index) max
        // within a thread, matching jnp.argmax.
        #pragma unroll 4
        for (int i = tid; i < NVEC; i += 256) {
            float4 v = __ldcs(p + i);
            int base = i << 2;
            if (v.x > best) { best = v.x; bidx = base;     }
            if (v.y > best) { best = v.y; bidx = base + 1; }
            if (v.z > best) { best = v.z; bidx = base + 2; }
            if (v.w > best) { best = v.w; bidx = base + 3; }
        }

        // Warp reduction (tie -> smaller index)
        #pragma unroll
        for (int off = 16; off > 0; off >>= 1) {
            float ov = __shfl_down_sync(0xFFFFFFFFu, best, off);
            int   oi = __shfl_down_sync(0xFFFFFFFFu, bidx, off);
            if (ov > best || (ov == best && oi < bidx)) { best = ov; bidx = oi; }
        }
        if (lid == 0) { s_val[wid] = best; s_idx[wid] = bidx; }
        __syncthreads();

        if (tid < 32) {
            best = (lid < 8) ? s_val[lid] : -3.402823466e+38f;
            bidx = (lid < 8) ? s_idx[lid] : 0x7FFFFFFF;
            #pragma unroll
            for (int off = 4; off > 0; off >>= 1) {
                float ov = __shfl_down_sync(0xFFFFFFFFu, best, off);
                int   oi = __shfl_down_sync(0xFFFFFFFFu, bidx, off);
                if (ov > best || (ov == best && oi < bidx)) { best = ov; bidx = oi; }
            }
            if (lid == 0) {
                const unsigned b = row / SEQ;
                atomicAdd(&g_hist[b * VOCAB + bidx], 1);
            }
        }
        __syncthreads();   // protect s_row / s_val reuse
    }

    // ---------- phase 2: grid-wide arrive + wait (all CTAs resident) ----------
    if (tid == 0) {
        __threadfence();                 // release: hist add visible before arrive
        atomicAdd(&g_done, 1u);
        // Wait with plain (non-atomic) polling + exponential backoff:
        // no LTS atomic-unit serialization, negligible L2 traffic.
        unsigned ns = 64;
        while (*(volatile unsigned*)&g_done < gridDim.x) {
            __nanosleep(ns);
            if (ns < 2048) ns <<= 1;
        }
    }
    __syncthreads();
    __threadfence();                     // acquire: all hist adds now visible

    // ---------- phase 3: finalize spread over all CTAs ----------
    const int stride = gridDim.x << 8;   // gridDim.x * 256
    for (int i = (blockIdx.x << 8) + tid; i < N4; i += stride) {
        int4* hp = reinterpret_cast<int4*>(g_hist) + i;
        int4 h = *hp;
        *hp = make_int4(0, 0, 0, 0);     // reset hist for next replay

        const int v0 = (i << 2) % VOCAB; // VOCAB % 4 == 0

        float4 o;
        o.x = (v0     <= 2) ? 0.0f : fminf((float)h.x, 4.0f) * 0.25f;
        o.y = (v0 + 1 <= 2) ? 0.0f : fminf((float)h.y, 4.0f) * 0.25f;
        o.z = (v0 + 2 <= 2) ? 0.0f : fminf((float)h.z, 4.0f) * 0.25f;
        o.w = (v0 + 3 <= 2) ? 0.0f : fminf((float)h.w, 4.0f) * 0.25f;
        reinterpret_cast<float4*>(out)[i] = o;
    }

    // ---------- phase 4: counter reset (last finisher) ----------
    // Safe vs. the phase-2 wait: g_fin reaches gridDim.x only after EVERY CTA
    // has passed its wait and finished finalize, so resetting g_done cannot
    // strand a waiter.
    if (tid == 0) {
        __threadfence();
        unsigned f = atomicAdd(&g_fin, 1u);
        if (f == gridDim.x - 1) {
            atomicExch(&g_next, 0u);
            atomicExch(&g_done, 0u);
            atomicExch(&g_fin,  0u);
        }
    }
}

extern "C" void kernel_launch(void* const* d_in, const int* in_sizes, int n_in,
                              void* d_out, int out_size) {
    const float* logits = (const float*)d_in[0];
    float* out = (float*)d_out;

    // Exactly-resident persistent grid: SMs * max occupancy for this kernel.
    int dev = 0;
    cudaGetDevice(&dev);
    int sms = 148;
    cudaDeviceGetAttribute(&sms, cudaDevAttrMultiProcessorCount, dev);
    int occ = 8;
    cudaOccupancyMaxActiveBlocksPerMultiprocessor(
        &occ, fused_persistent_kernel, 256, 0);
    int grid = sms * occ;
    if (grid > TOTAL) grid = TOTAL;

    fused_persistent_kernel<<<grid, 256>>>(logits, out);
}

// round 6
// speedup vs baseline: 1.0227x; 1.0227x over previous
#include <cuda_runtime.h>

#define VOCAB 32000
#define BATCH 4
#define SEQ   2048
#define NVEC  (VOCAB / 4)   // 8000 float4 per row

// Scratch histogram; reset to zero by a memset node before each replay.
__device__ int g_hist[BATCH * VOCAB];

// One CTA per (b, s) row: argmax over VOCAB, then write the FINAL output
// value directly via monotone atomicMax — no finalize kernel needed.
//
// out[b,v] = min(count,4)/4 is monotone nondecreasing in count, and all
// candidate values are non-negative floats (whose bit patterns compare like
// ints), so atomicMax(int) over per-increment values yields exactly the
// value at the final count, independent of arrival order.
__global__ __launch_bounds__(256, 8)
void argmax_hist_kernel(const float* __restrict__ logits,
                        float* __restrict__ out) {
    const int row = blockIdx.x;                       // 0 .. B*S-1
    const float4* __restrict__ p =
        reinterpret_cast<const float4*>(logits + (size_t)row * VOCAB);

    float best = -3.402823466e+38f;
    int   bidx = 0;
    const int tid = threadIdx.x;

    // Strided float4 scan, streaming (evict-first) loads. Strict '>' keeps
    // the first (lowest-index) max within a thread, matching jnp.argmax.
    #pragma unroll 4
    for (int i = tid; i < NVEC; i += 256) {
        float4 v = __ldcs(p + i);
        int base = i << 2;
        if (v.x > best) { best = v.x; bidx = base;     }
        if (v.y > best) { best = v.y; bidx = base + 1; }
        if (v.z > best) { best = v.z; bidx = base + 2; }
        if (v.w > best) { best = v.w; bidx = base + 3; }
    }

    // Warp reduction (tie -> smaller index)
    #pragma unroll
    for (int off = 16; off > 0; off >>= 1) {
        float ov = __shfl_down_sync(0xFFFFFFFFu, best, off);
        int   oi = __shfl_down_sync(0xFFFFFFFFu, bidx, off);
        if (ov > best || (ov == best && oi < bidx)) { best = ov; bidx = oi; }
    }

    __shared__ float s_val[8];
    __shared__ int   s_idx[8];
    const int wid = tid >> 5;
    const int lid = tid & 31;
    if (lid == 0) { s_val[wid] = best; s_idx[wid] = bidx; }
    __syncthreads();

    if (wid == 0) {
        best = (lid < 8) ? s_val[lid] : -3.402823466e+38f;
        bidx = (lid < 8) ? s_idx[lid] : 0x7FFFFFFF;
        #pragma unroll
        for (int off = 4; off > 0; off >>= 1) {
            float ov = __shfl_down_sync(0xFFFFFFFFu, best, off);
            int   oi = __shfl_down_sync(0xFFFFFFFFu, bidx, off);
            if (ov > best || (ov == best && oi < bidx)) { best = ov; bidx = oi; }
        }
        if (lid == 0) {
            const int bucket = (row / SEQ) * VOCAB + bidx;
            int old = atomicAdd(&g_hist[bucket], 1);
            if (bidx > 2) {   // PAD=0, START=1, END=2 stay 0 (from memset)
                float val = fminf((float)(old + 1), 4.0f) * 0.25f;
                atomicMax(reinterpret_cast<int*>(out) + bucket,
                          __float_as_int(val));
            }
        }
    }
}

extern "C" void kernel_launch(void* const* d_in, const int* in_sizes, int n_in,
                              void* d_out, int out_size) {
    const float* logits = (const float*)d_in[0];
    float* out = (float*)d_out;

    // Per-replay state reset via cheap memset nodes (graph-capturable).
    void* hist_ptr = nullptr;
    cudaGetSymbolAddress(&hist_ptr, g_hist);
    cudaMemsetAsync(out,      0, (size_t)BATCH * VOCAB * sizeof(float), 0);
    cudaMemsetAsync(hist_ptr, 0, (size_t)BATCH * VOCAB * sizeof(int),   0);

    argmax_hist_kernel<<<BATCH * SEQ, 256>>>(logits, out);
}